// round 13
// baseline (speedup 1.0000x reference)
#include <cuda_runtime.h>
#include <stdint.h>

// Geometry fixed by the problem: outputs/masks are [2,1,64,256,256]
#define HH 256
#define WW 256
#define BATCH 2
#define SLICES 128
#define WPR 8                        // 32-bit words per 256-px row
#define NWORDS 2048                  // words per slice
#define NPIX 65536                   // px per slice
#define TOTW (SLICES * NWORDS)
#define NCTA 1024                    // 8 CTAs per slice
#define THREADS 256
#define SSTRIDE 9                    // padded smem row stride (bank-conflict-free)

__device__ uint32_t g_mb[TOTW];      // mask bits (1 MB)
__device__ int      g_bs[TOTW];      // per-word LUT base (incl extra); -100 = slow
__device__ uint32_t g_hm[TOTW];      // per-word acc==ktop bitmask
__device__ uint32_t g_pl[5][TOTW];   // rare slow-path planes
__device__ int      g_extra[SLICES];
__device__ unsigned g_scnt[SLICES];  // pack-arrival counters (reset each run)
__device__ unsigned g_flag[SLICES];  // cascade-done flags   (reset each run)
__device__ double   g_cta[NCTA][3];
__device__ unsigned g_ticket = 0;

// dynamic smem (u32): mb[256*9] | buf0[256*9] | buf1[256*9] | planes[5][256*9]
#define SM_MB 0
#define SM_B0 2304
#define SM_B1 4608
#define SM_PL 6912
#define SMEM_BYTES ((6912 + 5 * 2304) * 4)   // 73728 B

__global__ __launch_bounds__(THREADS, 2)
void bbsd_mega_kernel(const float* __restrict__ outp, const int* __restrict__ mskp,
                      float* __restrict__ out) {
    extern __shared__ uint32_t dyn[];
    __shared__ float lut[64];
    __shared__ double r0s[8], r1s[8], r2s[8];
    __shared__ int s_leader, s_last;

    const int cta = blockIdx.x;
    const int slice = cta >> 3;
    const int oct = cta & 7;
    const int tid = threadIdx.x;
    const int lane = tid & 31;
    const int wid = tid >> 5;

    // weight LUT: acc 0..21; dist=(22-acc)/22; w=2/(1+exp(10*dist)); padded
    if (tid < 64) {
        int a = tid < 22 ? tid : 21;
        float dist = (22.0f - (float)a) / 22.0f;
        lut[tid] = 2.0f / (1.0f + expf(10.0f * dist));
    }

    // ---- issue output loads FIRST, pinned via asm (true MLP=8, in flight) ----
    const float4* op4 = reinterpret_cast<const float4*>(outp)
                      + (size_t)slice * (NPIX / 4) + oct * 2048;
    float4 va[8];
#pragma unroll
    for (int j = 0; j < 8; j++) {
        const float4* p = op4 + j * 256 + tid;
        asm volatile("ld.global.nc.v4.f32 {%0,%1,%2,%3}, [%4];"
                     : "=f"(va[j].x), "=f"(va[j].y), "=f"(va[j].z), "=f"(va[j].w)
                     : "l"(p));
    }

    // ---- pack this CTA's 1/8 slice of masks into g_mb ----
    const int4* mp4 = reinterpret_cast<const int4*>(mskp)
                    + (size_t)slice * (NPIX / 4) + oct * 2048;
#pragma unroll
    for (int j = 0; j < 8; j++) {
        int4 v = mp4[j * 256 + tid];
        unsigned nib = (v.x ? 1u : 0u) | (v.y ? 2u : 0u)
                     | (v.z ? 4u : 0u) | (v.w ? 8u : 0u);
        unsigned w = nib << ((lane & 7) * 4);
        w |= __shfl_xor_sync(0xffffffffu, w, 1);
        w |= __shfl_xor_sync(0xffffffffu, w, 2);
        w |= __shfl_xor_sync(0xffffffffu, w, 4);
        if ((lane & 7) == 0)
            g_mb[slice * NWORDS + ((oct * 2048 + j * 256 + tid) >> 3)] = w;
    }
    __threadfence();
    __syncthreads();
    if (tid == 0) {
        unsigned t = atomicAdd(&g_scnt[slice], 1u);
        s_leader = (t == 7u);                 // last arriver leads the cascade
    }
    __syncthreads();

    if (s_leader) {
        __threadfence();                      // acquire: see all 8 packers' bits
        uint32_t* mb = dyn + SM_MB;
        uint32_t* pl = dyn + SM_PL;
        // load slice bitmask (L2) into padded smem
#pragma unroll
        for (int j = 0; j < 8; j++) {
            int w = j * 256 + tid;
            mb[(w >> 3) * SSTRIDE + (w & 7)] = g_mb[slice * NWORDS + w];
        }
        __syncthreads();

        // edge (= round-0 acc) : thread owns one full row
        {
            const int r = tid;
            uint32_t m[8], u_[8], d_[8];
#pragma unroll
            for (int j = 0; j < 8; j++) {
                m[j] = mb[r * SSTRIDE + j];
                u_[j] = r ? mb[(r - 1) * SSTRIDE + j] : 0u;
                d_[j] = (r < HH - 1) ? mb[(r + 1) * SSTRIDE + j] : 0u;
            }
#pragma unroll
            for (int j = 0; j < 8; j++) {
                uint32_t pv = j ? m[j - 1] : 0u;
                uint32_t nx = (j < 7) ? m[j + 1] : 0u;
                uint32_t lf = (m[j] << 1) | (pv >> 31);
                uint32_t rt = (m[j] >> 1) | (nx << 31);
                uint32_t e = m[j] & ~(u_[j] & d_[j] & lf & rt);
                int idx = r * SSTRIDE + j;
                dyn[SM_B0 + idx] = e;
                pl[idx] = e;                  // P0 = edge (acc includes round 0)
                pl[2304 + idx] = 0u;
                pl[4608 + idx] = 0u;
                pl[6912 + idx] = 0u;
                pl[9216 + idx] = 0u;
            }
        }
        __syncthreads();

        // cascaded 3x3 OR-dilations with saturation early-exit
        int extra = 0;
        int sb = 0;
        for (int rd = 1; rd <= 20; rd++) {
            const uint32_t* src = dyn + (sb ? SM_B1 : SM_B0);
            uint32_t* dst = dyn + (sb ? SM_B0 : SM_B1);
            const int r = tid;
            uint32_t vo[10];
            vo[0] = 0u; vo[9] = 0u;
#pragma unroll
            for (int j = 0; j < 8; j++) {
                uint32_t v = src[r * SSTRIDE + j];
                if (r)          v |= src[(r - 1) * SSTRIDE + j];
                if (r < HH - 1) v |= src[(r + 1) * SSTRIDE + j];
                vo[j + 1] = v;
            }
            uint32_t allw = 0xffffffffu;
#pragma unroll
            for (int j = 0; j < 8; j++) {
                uint32_t c = vo[j + 1];
                uint32_t nw = c | (c << 1) | (vo[j] >> 31) | (c >> 1) | (vo[j + 2] << 31);
                int idx = r * SSTRIDE + j;
                dst[idx] = nw;
                allw &= nw;
                uint32_t cy = nw, t;          // ripple-carry +1 where covered
                t = pl[idx] & cy;        pl[idx] ^= cy;        cy = t;
                t = pl[2304 + idx] & cy; pl[2304 + idx] ^= cy; cy = t;
                t = pl[4608 + idx] & cy; pl[4608 + idx] ^= cy; cy = t;
                t = pl[6912 + idx] & cy; pl[6912 + idx] ^= cy; cy = t;
                pl[9216 + idx] ^= cy;
            }
            sb ^= 1;
            if (__syncthreads_and(allw == 0xffffffffu)) { extra = 20 - rd; break; }
        }
        if (tid == 0) g_extra[slice] = extra;

        // per-word metadata for the whole slice: acc two-valued {kt-1, kt}
#pragma unroll
        for (int j = 0; j < 8; j++) {
            int w = j * 256 + tid;
            int idx = (w >> 3) * SSTRIDE + (w & 7);
            uint32_t p0 = pl[idx], p1 = pl[2304 + idx], p2 = pl[4608 + idx],
                     p3 = pl[6912 + idx], p4 = pl[9216 + idx];
            unsigned kt = ((p0 >> 31) & 1u) | (((p1 >> 31) & 1u) << 1)
                        | (((p2 >> 31) & 1u) << 2) | (((p3 >> 31) & 1u) << 3)
                        | (((p4 >> 31) & 1u) << 4);
            uint32_t mhi = ((kt & 1u)  ? p0 : ~p0) & ((kt & 2u)  ? p1 : ~p1)
                         & ((kt & 4u)  ? p2 : ~p2) & ((kt & 8u)  ? p3 : ~p3)
                         & ((kt & 16u) ? p4 : ~p4);
            uint32_t mlo = 0u;
            if (kt) {
                unsigned kl = kt - 1u;
                mlo = ((kl & 1u)  ? p0 : ~p0) & ((kl & 2u)  ? p1 : ~p1)
                    & ((kl & 4u)  ? p2 : ~p2) & ((kl & 8u)  ? p3 : ~p3)
                    & ((kl & 16u) ? p4 : ~p4);
            }
            bool valid = (mhi | mlo) == 0xffffffffu;
            int gi = slice * NWORDS + w;
            g_bs[gi] = valid ? ((int)kt - 1 + extra) : -100;
            g_hm[gi] = mhi;
            if (!valid) {
                g_pl[0][gi] = p0; g_pl[1][gi] = p1; g_pl[2][gi] = p2;
                g_pl[3][gi] = p3; g_pl[4][gi] = p4;
            }
        }
        __threadfence();
        __syncthreads();
        if (tid == 0) atomicExch(&g_flag[slice], 1u);   // release
    } else {
        if (tid == 0) {
            while (atomicAdd(&g_flag[slice], 0u) == 0u) __nanosleep(128);
        }
        __syncthreads();
        __threadfence();                      // acquire
    }

    const int extra = g_extra[slice];

    // ---- decode: outputs already in registers; meta is L2-hot ----
    float s_ia = 0.f, s_in = 0.f, s_ta = 0.f;
#pragma unroll
    for (int j = 0; j < 8; j++) {
        int lw = slice * NWORDS + oct * 256 + j * 32 + (tid >> 3);
        int i0 = (tid & 7) * 4;
        int bs = g_bs[lw];
        uint32_t qm = g_mb[lw] >> i0;
        float vv[4] = {va[j].x, va[j].y, va[j].z, va[j].w};
        if (bs != -100) {
            uint32_t qh = g_hm[lw] >> i0;
#pragma unroll
            for (int e = 0; e < 4; e++) {
                float w = lut[bs + (int)((qh >> e) & 1u)];
                float f = vv[e] * w;
                s_ia += f;
                if ((qm >> e) & 1u) { s_in += f; s_ta += w; }
            }
        } else {
            uint32_t q0 = g_pl[0][lw] >> i0;
            uint32_t q1 = g_pl[1][lw] >> i0;
            uint32_t q2 = g_pl[2][lw] >> i0;
            uint32_t q3 = g_pl[3][lw] >> i0;
            uint32_t q4 = g_pl[4][lw] >> i0;
#pragma unroll
            for (int e = 0; e < 4; e++) {
                unsigned a = ((q0 >> e) & 1u)
                           | (((q1 >> e) & 1u) << 1)
                           | (((q2 >> e) & 1u) << 2)
                           | (((q3 >> e) & 1u) << 3)
                           | (((q4 >> e) & 1u) << 4);
                float w = lut[a + extra];
                float f = vv[e] * w;
                s_ia += f;
                if ((qm >> e) & 1u) { s_in += f; s_ta += w; }
            }
        }
    }

    // ---- reduce to per-CTA partials ----
    double d0 = (double)s_in, d1 = (double)s_ia, d2 = (double)s_ta;
#pragma unroll
    for (int o = 16; o > 0; o >>= 1) {
        d0 += __shfl_down_sync(0xffffffffu, d0, o);
        d1 += __shfl_down_sync(0xffffffffu, d1, o);
        d2 += __shfl_down_sync(0xffffffffu, d2, o);
    }
    if (lane == 0) { r0s[wid] = d0; r1s[wid] = d1; r2s[wid] = d2; }
    __syncthreads();
    if (wid == 0) {
        double a0 = (lane < 8) ? r0s[lane] : 0.0;
        double a1 = (lane < 8) ? r1s[lane] : 0.0;
        double a2 = (lane < 8) ? r2s[lane] : 0.0;
#pragma unroll
        for (int o = 4; o > 0; o >>= 1) {
            a0 += __shfl_down_sync(0xffffffffu, a0, o);
            a1 += __shfl_down_sync(0xffffffffu, a1, o);
            a2 += __shfl_down_sync(0xffffffffu, a2, o);
        }
        if (lane == 0) {
            g_cta[cta][0] = a0;
            g_cta[cta][1] = a1;
            g_cta[cta][2] = a2;
        }
    }

    // ---- fused finalize: last-arriving CTA computes loss + resets state ----
    if (tid == 0) {
        __threadfence();
        unsigned t = atomicAdd(&g_ticket, 1u);
        s_last = (t == NCTA - 1);
    }
    __syncthreads();
    if (s_last) {
        __threadfence();
        __shared__ double fin[3][8];
        double loss = 0.0;
        for (int b = 0; b < BATCH; b++) {
            int j0 = b * 512 + tid;           // batch b owns CTAs [b*512, b*512+512)
            double i0 = g_cta[j0][0] + g_cta[j0 + 256][0];
            double a0 = g_cta[j0][1] + g_cta[j0 + 256][1];
            double t0 = g_cta[j0][2] + g_cta[j0 + 256][2];
#pragma unroll
            for (int o = 16; o > 0; o >>= 1) {
                i0 += __shfl_down_sync(0xffffffffu, i0, o);
                a0 += __shfl_down_sync(0xffffffffu, a0, o);
                t0 += __shfl_down_sync(0xffffffffu, t0, o);
            }
            if (lane == 0) { fin[0][wid] = i0; fin[1][wid] = a0; fin[2][wid] = t0; }
            __syncthreads();
            if (tid == 0) {
                double I = 0.0, A = 0.0, T = 0.0;
#pragma unroll
                for (int q = 0; q < 8; q++) { I += fin[0][q]; A += fin[1][q]; T += fin[2][q]; }
                loss += (T == 0.0) ? 0.0 : (1.0 - 2.0 * I / (A + T + 2.0e-6));
            }
            __syncthreads();
        }
        // reset per-run state for graph replays
        if (tid < SLICES) { g_scnt[tid] = 0u; g_flag[tid] = 0u; }
        if (tid == 0) {
            out[0] = (float)(loss * 0.5);     // mean over BATCH=2
            g_ticket = 0u;
        }
    }
}

extern "C" void kernel_launch(void* const* d_in, const int* in_sizes, int n_in,
                              void* d_out, int out_size) {
    const float* outputs = (const float*)d_in[0];  // float32 [2,1,64,256,256]
    const int*   masks   = (const int*)d_in[1];    // int32   [2,1,64,256,256]
    float* out = (float*)d_out;

    cudaFuncSetAttribute(bbsd_mega_kernel,
                         cudaFuncAttributeMaxDynamicSharedMemorySize, SMEM_BYTES);
    bbsd_mega_kernel<<<NCTA, THREADS, SMEM_BYTES>>>(outputs, masks, out);
}

// round 14
// speedup vs baseline: 1.8427x; 1.8427x over previous
#include <cuda_runtime.h>
#include <stdint.h>

// Geometry fixed by the problem: outputs/masks are [2,1,64,256,256]
#define HH 256
#define WW 256
#define BATCH 2
#define SLICES 128
#define WPR 8                        // 32-bit words per 256-px row
#define NWORDS 2048                  // words per slice
#define NPIX 65536                   // px per slice
#define TOTW (SLICES * NWORDS)       // 262144
#define NCTA 1024                    // pack/decode grid (8 CTAs per slice)

__device__ uint32_t g_mb[TOTW];      // mask bits (1 MB)
__device__ uint2    g_meta[TOTW];    // .x = LUT base (int, incl extra; -100 = slow), .y = acc==ktop mask
__device__ uint32_t g_pl[5][TOTW];   // rare slow-path planes (acc incl. edge)
__device__ int      g_extra[SLICES];
__device__ double   g_cta[NCTA][3];
__device__ unsigned g_ticket = 0;

// ================= K1: pack masks -> bits (round-11 proven 5.2 TB/s shape) ===
__global__ __launch_bounds__(256)
void pack_kernel(const int* __restrict__ mskp) {
    const int tid = threadIdx.x;
    const int lane = tid & 31;
    const int4* mp4 = reinterpret_cast<const int4*>(mskp);
    const size_t gbase = (size_t)blockIdx.x * 2048;   // int4 groups per CTA

#pragma unroll
    for (int h = 0; h < 2; h++) {
        int4 va[4];
#pragma unroll
        for (int j = 0; j < 4; j++)                   // 4 back-to-back LDG.128
            va[j] = mp4[gbase + (size_t)(h * 4 + j) * 256 + tid];
#pragma unroll
        for (int j = 0; j < 4; j++) {
            int4 v = va[j];
            unsigned nib = (v.x ? 1u : 0u) | (v.y ? 2u : 0u)
                         | (v.z ? 4u : 0u) | (v.w ? 8u : 0u);
            unsigned w = nib << ((lane & 7) * 4);
            w |= __shfl_xor_sync(0xffffffffu, w, 1);
            w |= __shfl_xor_sync(0xffffffffu, w, 2);
            w |= __shfl_xor_sync(0xffffffffu, w, 4);
            size_t g = gbase + (size_t)(h * 4 + j) * 256 + tid;
            if ((lane & 7) == 0) g_mb[g >> 3] = w;
        }
    }
}

// ================= K2: per-slice cascade + per-word metadata ==================
__global__ __launch_bounds__(1024, 1)
void cascade_kernel() {
    __shared__ uint32_t mb[NWORDS];
    __shared__ uint32_t buf[2][NWORDS];

    const int slice = blockIdx.x;
    const int tid = threadIdx.x;

#pragma unroll
    for (int j = 0; j < 2; j++)
        mb[j * 1024 + tid] = g_mb[slice * NWORDS + j * 1024 + tid];
    __syncthreads();

    // thread owns a quarter-row: 2 consecutive words
    const int row = tid >> 2;
    const int cw0 = (tid & 3) * 2;
    const int wb = row * WPR + cw0;

    uint32_t P0[2], P1[2], P2[2], P3[2], P4[2];     // acc (incl. edge), bit-sliced

    // edge = m & ~(up & down & left & right); P0 init = edge (round-0 term)
#pragma unroll
    for (int j = 0; j < 2; j++) {
        int cw = cw0 + j, gw = wb + j;
        uint32_t m  = mb[gw];
        uint32_t up = row            ? mb[gw - WPR] : 0u;
        uint32_t dn = (row < HH - 1) ? mb[gw + WPR] : 0u;
        uint32_t pv = cw             ? mb[gw - 1]   : 0u;
        uint32_t nx = (cw < WPR - 1) ? mb[gw + 1]   : 0u;
        uint32_t lf = (m << 1) | (pv >> 31);
        uint32_t rt = (m >> 1) | (nx << 31);
        uint32_t e = m & ~(up & dn & lf & rt);
        buf[0][gw] = e;
        P0[j] = e; P1[j] = 0u; P2[j] = 0u; P3[j] = 0u; P4[j] = 0u;
    }
    __syncthreads();

    // cascaded 3x3 OR-dilations with saturation early-exit
    int extra = 0;
    int sb = 0;
    for (int r = 1; r <= 20; r++) {
        const uint32_t* src = buf[sb];
        uint32_t* dst = buf[sb ^ 1];
        uint32_t va[4];
#pragma unroll
        for (int k = 0; k < 4; k++) {
            int cw = cw0 + k - 1;
            uint32_t v = 0u;
            if (cw >= 0 && cw < WPR) {
                int gw = row * WPR + cw;
                v = src[gw];
                if (row)          v |= src[gw - WPR];
                if (row < HH - 1) v |= src[gw + WPR];
            }
            va[k] = v;
        }
        uint32_t allw = 0xffffffffu;
#pragma unroll
        for (int j = 0; j < 2; j++) {
            uint32_t c = va[j + 1];
            uint32_t nw = c | (c << 1) | (va[j] >> 31) | (c >> 1) | (va[j + 2] << 31);
            dst[wb + j] = nw;
            allw &= nw;
            uint32_t cy = nw, t;                    // ripple-carry +1 where covered
            t = P0[j] & cy; P0[j] ^= cy; cy = t;
            t = P1[j] & cy; P1[j] ^= cy; cy = t;
            t = P2[j] & cy; P2[j] ^= cy; cy = t;
            t = P3[j] & cy; P3[j] ^= cy; cy = t;
            P4[j] ^= cy;
        }
        sb ^= 1;
        if (__syncthreads_and(allw == 0xffffffffu)) { extra = 20 - r; break; }
    }
    if (tid == 0) g_extra[slice] = extra;

    // per-word metadata: acc two-valued {kt-1, kt} (typical; edge already folded)
#pragma unroll
    for (int j = 0; j < 2; j++) {
        int gw = wb + j;
        uint32_t p0 = P0[j], p1 = P1[j], p2 = P2[j], p3 = P3[j], p4 = P4[j];
        unsigned kt = ((p0 >> 31) & 1u) | (((p1 >> 31) & 1u) << 1)
                    | (((p2 >> 31) & 1u) << 2) | (((p3 >> 31) & 1u) << 3)
                    | (((p4 >> 31) & 1u) << 4);
        uint32_t mhi = ((kt & 1u)  ? p0 : ~p0) & ((kt & 2u)  ? p1 : ~p1)
                     & ((kt & 4u)  ? p2 : ~p2) & ((kt & 8u)  ? p3 : ~p3)
                     & ((kt & 16u) ? p4 : ~p4);
        uint32_t mlo = 0u;
        if (kt) {
            unsigned kl = kt - 1u;
            mlo = ((kl & 1u)  ? p0 : ~p0) & ((kl & 2u)  ? p1 : ~p1)
                & ((kl & 4u)  ? p2 : ~p2) & ((kl & 8u)  ? p3 : ~p3)
                & ((kl & 16u) ? p4 : ~p4);
        }
        bool valid = (mhi | mlo) == 0xffffffffu;
        int gi = slice * NWORDS + gw;
        uint2 mt;
        mt.x = (uint32_t)(valid ? ((int)kt - 1 + extra) : -100);
        mt.y = mhi;
        g_meta[gi] = mt;
        if (!valid) {                               // rare: spill planes
            g_pl[0][gi] = p0; g_pl[1][gi] = p1; g_pl[2][gi] = p2;
            g_pl[3][gi] = p3; g_pl[4][gi] = p4;
        }
    }
}

// ================= K3: decode + weighted sums + finalize ======================
__global__ __launch_bounds__(256)
void decode_kernel(const float* __restrict__ outp, float* __restrict__ out) {
    __shared__ float lut[64];
    __shared__ double r0s[8], r1s[8], r2s[8];
    __shared__ int s_last;

    const int cta = blockIdx.x;
    const int slice = cta >> 3;                     // 8 CTAs per slice
    const int tid = threadIdx.x;
    const int lane = tid & 31;
    const int wid = tid >> 5;

    if (tid < 64) {
        int a = tid < 22 ? tid : 21;
        float dist = (22.0f - (float)a) / 22.0f;
        lut[tid] = 2.0f / (1.0f + expf(10.0f * dist));
    }
    __syncthreads();

    const float4* op4 = reinterpret_cast<const float4*>(outp);
    const size_t gbase = (size_t)cta * 2048;        // float4 groups per CTA
    const int extra = g_extra[slice];

    float s_ia = 0.f, s_in = 0.f, s_ta = 0.f;
#pragma unroll
    for (int h = 0; h < 2; h++) {
        // front-batch 4 data LDG.128 + 4 mask LDG.32 + 4 meta LDG.64 (L2-hot)
        float4 va[4];
        uint32_t mbv[4];
        uint2 mt[4];
#pragma unroll
        for (int j = 0; j < 4; j++)
            va[j] = op4[gbase + (size_t)(h * 4 + j) * 256 + tid];
#pragma unroll
        for (int j = 0; j < 4; j++) {
            size_t w = (gbase + (size_t)(h * 4 + j) * 256 + tid) >> 3;
            mbv[j] = g_mb[w];
            mt[j] = g_meta[w];
        }
#pragma unroll
        for (int j = 0; j < 4; j++) {
            size_t g = gbase + (size_t)(h * 4 + j) * 256 + tid;
            int i0 = ((int)g & 7) * 4;
            int bs = (int)mt[j].x;
            uint32_t qm = mbv[j] >> i0;
            float vv[4] = {va[j].x, va[j].y, va[j].z, va[j].w};
            if (bs != -100) {
                uint32_t qh = mt[j].y >> i0;
#pragma unroll
                for (int e = 0; e < 4; e++) {
                    float w = lut[bs + (int)((qh >> e) & 1u)];
                    float f = vv[e] * w;
                    s_ia += f;
                    if ((qm >> e) & 1u) { s_in += f; s_ta += w; }
                }
            } else {
                size_t wdx = g >> 3;
                uint32_t q0 = g_pl[0][wdx] >> i0;
                uint32_t q1 = g_pl[1][wdx] >> i0;
                uint32_t q2 = g_pl[2][wdx] >> i0;
                uint32_t q3 = g_pl[3][wdx] >> i0;
                uint32_t q4 = g_pl[4][wdx] >> i0;
#pragma unroll
                for (int e = 0; e < 4; e++) {
                    unsigned a = ((q0 >> e) & 1u)
                               | (((q1 >> e) & 1u) << 1)
                               | (((q2 >> e) & 1u) << 2)
                               | (((q3 >> e) & 1u) << 3)
                               | (((q4 >> e) & 1u) << 4);
                    float w = lut[a + extra];
                    float f = vv[e] * w;
                    s_ia += f;
                    if ((qm >> e) & 1u) { s_in += f; s_ta += w; }
                }
            }
        }
    }

    // CTA reduce -> g_cta[cta]
    double d0 = (double)s_in, d1 = (double)s_ia, d2 = (double)s_ta;
#pragma unroll
    for (int o = 16; o > 0; o >>= 1) {
        d0 += __shfl_down_sync(0xffffffffu, d0, o);
        d1 += __shfl_down_sync(0xffffffffu, d1, o);
        d2 += __shfl_down_sync(0xffffffffu, d2, o);
    }
    if (lane == 0) { r0s[wid] = d0; r1s[wid] = d1; r2s[wid] = d2; }
    __syncthreads();
    if (wid == 0) {
        double a0 = (lane < 8) ? r0s[lane] : 0.0;
        double a1 = (lane < 8) ? r1s[lane] : 0.0;
        double a2 = (lane < 8) ? r2s[lane] : 0.0;
#pragma unroll
        for (int o = 4; o > 0; o >>= 1) {
            a0 += __shfl_down_sync(0xffffffffu, a0, o);
            a1 += __shfl_down_sync(0xffffffffu, a1, o);
            a2 += __shfl_down_sync(0xffffffffu, a2, o);
        }
        if (lane == 0) {
            g_cta[cta][0] = a0;
            g_cta[cta][1] = a1;
            g_cta[cta][2] = a2;
        }
    }

    // last-arriving CTA finalizes the scalar loss
    if (tid == 0) {
        __threadfence();
        unsigned t = atomicAdd(&g_ticket, 1u);
        s_last = (t == NCTA - 1);
    }
    __syncthreads();
    if (s_last) {
        __threadfence();
        __shared__ double fin[3][8];
        double loss = 0.0;
        for (int b = 0; b < BATCH; b++) {
            int j0 = b * 512 + tid;                 // batch b owns CTAs [b*512, b*512+512)
            double i0 = g_cta[j0][0] + g_cta[j0 + 256][0];
            double a0 = g_cta[j0][1] + g_cta[j0 + 256][1];
            double t0 = g_cta[j0][2] + g_cta[j0 + 256][2];
#pragma unroll
            for (int o = 16; o > 0; o >>= 1) {
                i0 += __shfl_down_sync(0xffffffffu, i0, o);
                a0 += __shfl_down_sync(0xffffffffu, a0, o);
                t0 += __shfl_down_sync(0xffffffffu, t0, o);
            }
            if (lane == 0) { fin[0][wid] = i0; fin[1][wid] = a0; fin[2][wid] = t0; }
            __syncthreads();
            if (tid == 0) {
                double I = 0.0, A = 0.0, T = 0.0;
#pragma unroll
                for (int q = 0; q < 8; q++) { I += fin[0][q]; A += fin[1][q]; T += fin[2][q]; }
                loss += (T == 0.0) ? 0.0 : (1.0 - 2.0 * I / (A + T + 2.0e-6));
            }
            __syncthreads();
        }
        if (tid == 0) {
            out[0] = (float)(loss * 0.5);           // mean over BATCH=2
            g_ticket = 0;                           // reset for next graph replay
        }
    }
}

extern "C" void kernel_launch(void* const* d_in, const int* in_sizes, int n_in,
                              void* d_out, int out_size) {
    const float* outputs = (const float*)d_in[0];  // float32 [2,1,64,256,256]
    const int*   masks   = (const int*)d_in[1];    // int32   [2,1,64,256,256]
    float* out = (float*)d_out;

    pack_kernel<<<NCTA, 256>>>(masks);
    cascade_kernel<<<SLICES, 1024>>>();
    decode_kernel<<<NCTA, 256>>>(outputs, out);
}

// round 15
// speedup vs baseline: 1.8481x; 1.0029x over previous
#include <cuda_runtime.h>
#include <stdint.h>

// Geometry fixed by the problem: outputs/masks are [2,1,64,256,256]
#define HH 256
#define BATCH 2
#define SLICES 128
#define NWORDS 2048                  // words per slice
#define TOTW (SLICES * NWORDS)       // 262144 32-bit words
#define NCTAS 512                    // 4/SM resident (guaranteed by launch_bounds+smem)
#define THREADS 256
#define NGROUPS 2097152              // total int4/float4 groups (2 batches x 1M)

__device__ uint32_t g_mb[TOTW];      // mask bits (1 MB)
__device__ uint2    g_meta[TOTW];    // .x = LUT base (incl extra; -100 = slow), .y = acc==ktop mask
__device__ uint32_t g_pl[4][TOTW];   // rare slow-path planes (acc incl. edge, <=15)
__device__ int      g_extra[SLICES];
__device__ double   g_cta[NCTAS][3];
__device__ unsigned g_bar1 = 0, g_bar2 = 0, g_ticket = 0;

// dynamic smem (u32): buf0[2048] | buf1[2048] | planes[4][2048]  = 48 KB
#define SB0 0
#define SB1 2048
#define SPL 4096
#define SMEM_BYTES 49152

__device__ __forceinline__ void grid_bar(unsigned* ctr) {
    __syncthreads();
    if (threadIdx.x == 0) {
        __threadfence();
        unsigned t = atomicAdd(ctr, 1u) + 1u;
        if (t < NCTAS)
            while (*(volatile unsigned*)ctr < NCTAS) __nanosleep(64);
        __threadfence();
    }
    __syncthreads();
}

__global__ __launch_bounds__(THREADS, 4)
void bbsd_one_kernel(const float* __restrict__ outp, const int* __restrict__ mskp,
                     float* __restrict__ out) {
    extern __shared__ uint32_t dyn[];
    __shared__ float lut[64];
    __shared__ double r0s[8], r1s[8], r2s[8];
    __shared__ int s_last;

    const int cta = blockIdx.x;
    const int tid = threadIdx.x;
    const int lane = tid & 31;
    const int wid = tid >> 5;
    const int batch = cta >> 8;                     // 0 or 1 (256 CTAs per batch)
    const size_t gstripe = (size_t)(batch << 20) + (size_t)(cta & 255) * 256 + tid;

    // weight LUT: acc 0..21; dist=(22-acc)/22; w=2/(1+exp(10*dist)); padded
    if (tid < 64) {
        int a = tid < 22 ? tid : 21;
        float dist = (22.0f - (float)a) / 22.0f;
        lut[tid] = 2.0f / (1.0f + expf(10.0f * dist));
    }

    // ============ Phase A: pack masks + prefetch outputs into L2 ============
    // L2 prefetch of this thread's 256-byte output span (fire-and-forget)
    {
        const char* pf = (const char*)outp + ((size_t)(cta * 256 + tid)) * 256;
        asm volatile("prefetch.global.L2 [%0];" :: "l"(pf));
        asm volatile("prefetch.global.L2 [%0];" :: "l"(pf + 128));
    }
    const int4* mp4 = reinterpret_cast<const int4*>(mskp);
#pragma unroll
    for (int h = 0; h < 4; h++) {
        int4 va[4];
#pragma unroll
        for (int j = 0; j < 4; j++)                 // 4 back-to-back LDG.128
            va[j] = mp4[gstripe + (size_t)(h * 4 + j) * 65536];
#pragma unroll
        for (int j = 0; j < 4; j++) {
            int4 v = va[j];
            unsigned nib = (v.x ? 1u : 0u) | (v.y ? 2u : 0u)
                         | (v.z ? 4u : 0u) | (v.w ? 8u : 0u);
            unsigned w = nib << ((lane & 7) * 4);
            w |= __shfl_xor_sync(0xffffffffu, w, 1);
            w |= __shfl_xor_sync(0xffffffffu, w, 2);
            w |= __shfl_xor_sync(0xffffffffu, w, 4);
            size_t g = gstripe + (size_t)(h * 4 + j) * 65536;
            if ((lane & 7) == 0) g_mb[g >> 3] = w;
        }
    }
    grid_bar(&g_bar1);

    // ============ Phase B: cascade (CTAs 0..127, one slice each) ============
    if (cta < SLICES) {
        const int slice = cta;
        // scattered ownership: word w = j*256 + tid (conflict-free smem)
        // edge = m & ~(up & dn & lf & rt); P0 init = edge (round-0 term)
#pragma unroll
        for (int j = 0; j < 8; j++) {
            int w = j * 256 + tid;
            int row = w >> 3, col = w & 7;
            int gi = slice * NWORDS + w;
            uint32_t m  = g_mb[gi];
            uint32_t up = row            ? g_mb[gi - 8] : 0u;
            uint32_t dn = (row < HH - 1) ? g_mb[gi + 8] : 0u;
            uint32_t pv = col            ? g_mb[gi - 1] : 0u;
            uint32_t nx = (col < 7)      ? g_mb[gi + 1] : 0u;
            uint32_t lf = (m << 1) | (pv >> 31);
            uint32_t rt = (m >> 1) | (nx << 31);
            uint32_t e = m & ~(up & dn & lf & rt);
            dyn[SB0 + w] = e;
            dyn[SPL + w] = e;                       // P0
            dyn[SPL + 2048 + w] = 0u;               // P1
            dyn[SPL + 4096 + w] = 0u;               // P2
            dyn[SPL + 6144 + w] = 0u;               // P3
        }
        __syncthreads();

        int extra = 0;
        int sb = 0;
        for (int r = 1; r <= 20; r++) {
            const uint32_t* src = dyn + (sb ? SB1 : SB0);
            uint32_t* dst = dyn + (sb ? SB0 : SB1);
            uint32_t allw = 0xffffffffu;
#pragma unroll
            for (int j = 0; j < 8; j++) {
                int w = j * 256 + tid;
                int row = w >> 3, col = w & 7;
                uint32_t vc = src[w];
                if (row)          vc |= src[w - 8];
                if (row < HH - 1) vc |= src[w + 8];
                uint32_t vl = 0u, vr = 0u;
                if (col) {
                    vl = src[w - 1];
                    if (row)          vl |= src[w - 9];
                    if (row < HH - 1) vl |= src[w + 7];
                }
                if (col < 7) {
                    vr = src[w + 1];
                    if (row)          vr |= src[w - 7];
                    if (row < HH - 1) vr |= src[w + 9];
                }
                uint32_t nw = vc | (vc << 1) | (vl >> 31) | (vc >> 1) | (vr << 31);
                dst[w] = nw;
                allw &= nw;
                // ripple-carry +1 into 4 smem planes where covered
                uint32_t cy = nw, p, t;
                p = dyn[SPL + w];        t = p & cy; dyn[SPL + w] = p ^ cy;        cy = t;
                p = dyn[SPL + 2048 + w]; t = p & cy; dyn[SPL + 2048 + w] = p ^ cy; cy = t;
                p = dyn[SPL + 4096 + w]; t = p & cy; dyn[SPL + 4096 + w] = p ^ cy; cy = t;
                p = dyn[SPL + 6144 + w];             dyn[SPL + 6144 + w] = p ^ cy;
            }
            sb ^= 1;
            if (__syncthreads_and(allw == 0xffffffffu)) { extra = 20 - r; break; }
        }
        if (tid == 0) g_extra[slice] = extra;

        // per-word metadata: acc two-valued {kt-1, kt} typical (edge folded in)
#pragma unroll
        for (int j = 0; j < 8; j++) {
            int w = j * 256 + tid;
            uint32_t p0 = dyn[SPL + w], p1 = dyn[SPL + 2048 + w],
                     p2 = dyn[SPL + 4096 + w], p3 = dyn[SPL + 6144 + w];
            unsigned kt = ((p0 >> 31) & 1u) | (((p1 >> 31) & 1u) << 1)
                        | (((p2 >> 31) & 1u) << 2) | (((p3 >> 31) & 1u) << 3);
            uint32_t mhi = ((kt & 1u) ? p0 : ~p0) & ((kt & 2u) ? p1 : ~p1)
                         & ((kt & 4u) ? p2 : ~p2) & ((kt & 8u) ? p3 : ~p3);
            uint32_t mlo = 0u;
            if (kt) {
                unsigned kl = kt - 1u;
                mlo = ((kl & 1u) ? p0 : ~p0) & ((kl & 2u) ? p1 : ~p1)
                    & ((kl & 4u) ? p2 : ~p2) & ((kl & 8u) ? p3 : ~p3);
            }
            bool valid = (mhi | mlo) == 0xffffffffu;
            int gi = slice * NWORDS + w;
            uint2 mt;
            mt.x = (uint32_t)(valid ? ((int)kt - 1 + extra) : -100);
            mt.y = mhi;
            g_meta[gi] = mt;
            if (!valid) {
                g_pl[0][gi] = p0; g_pl[1][gi] = p1;
                g_pl[2][gi] = p2; g_pl[3][gi] = p3;
            }
        }
    }
    grid_bar(&g_bar2);

    // ============ Phase C: decode (outputs are L2-resident) ============
    const float4* op4 = reinterpret_cast<const float4*>(outp);
    float s_ia = 0.f, s_in = 0.f, s_ta = 0.f;
#pragma unroll
    for (int h = 0; h < 4; h++) {
        float4 va[4];
        uint32_t mbv[4];
        uint2 mt[4];
#pragma unroll
        for (int j = 0; j < 4; j++)
            va[j] = op4[gstripe + (size_t)(h * 4 + j) * 65536];
#pragma unroll
        for (int j = 0; j < 4; j++) {
            size_t w = (gstripe + (size_t)(h * 4 + j) * 65536) >> 3;
            mbv[j] = g_mb[w];
            mt[j] = g_meta[w];
        }
#pragma unroll
        for (int j = 0; j < 4; j++) {
            size_t g = gstripe + (size_t)(h * 4 + j) * 65536;
            int i0 = ((int)g & 7) * 4;
            int bs = (int)mt[j].x;
            uint32_t qm = mbv[j] >> i0;
            float vv[4] = {va[j].x, va[j].y, va[j].z, va[j].w};
            if (bs != -100) {
                uint32_t qh = mt[j].y >> i0;
#pragma unroll
                for (int e = 0; e < 4; e++) {
                    float w = lut[bs + (int)((qh >> e) & 1u)];
                    float f = vv[e] * w;
                    s_ia += f;
                    if ((qm >> e) & 1u) { s_in += f; s_ta += w; }
                }
            } else {
                size_t wdx = g >> 3;
                int slice = (int)(g >> 14);
                int extra = g_extra[slice];
                uint32_t q0 = g_pl[0][wdx] >> i0;
                uint32_t q1 = g_pl[1][wdx] >> i0;
                uint32_t q2 = g_pl[2][wdx] >> i0;
                uint32_t q3 = g_pl[3][wdx] >> i0;
#pragma unroll
                for (int e = 0; e < 4; e++) {
                    unsigned a = ((q0 >> e) & 1u)
                               | (((q1 >> e) & 1u) << 1)
                               | (((q2 >> e) & 1u) << 2)
                               | (((q3 >> e) & 1u) << 3);
                    float w = lut[a + extra];
                    float f = vv[e] * w;
                    s_ia += f;
                    if ((qm >> e) & 1u) { s_in += f; s_ta += w; }
                }
            }
        }
    }

    // CTA reduce -> g_cta[cta]  (CTA's pixels lie entirely in one batch)
    double d0 = (double)s_in, d1 = (double)s_ia, d2 = (double)s_ta;
#pragma unroll
    for (int o = 16; o > 0; o >>= 1) {
        d0 += __shfl_down_sync(0xffffffffu, d0, o);
        d1 += __shfl_down_sync(0xffffffffu, d1, o);
        d2 += __shfl_down_sync(0xffffffffu, d2, o);
    }
    if (lane == 0) { r0s[wid] = d0; r1s[wid] = d1; r2s[wid] = d2; }
    __syncthreads();
    if (wid == 0) {
        double a0 = (lane < 8) ? r0s[lane] : 0.0;
        double a1 = (lane < 8) ? r1s[lane] : 0.0;
        double a2 = (lane < 8) ? r2s[lane] : 0.0;
#pragma unroll
        for (int o = 4; o > 0; o >>= 1) {
            a0 += __shfl_down_sync(0xffffffffu, a0, o);
            a1 += __shfl_down_sync(0xffffffffu, a1, o);
            a2 += __shfl_down_sync(0xffffffffu, a2, o);
        }
        if (lane == 0) {
            g_cta[cta][0] = a0;
            g_cta[cta][1] = a1;
            g_cta[cta][2] = a2;
        }
    }

    // ============ finalize: last-arriving CTA; reset state for replay ========
    if (tid == 0) {
        __threadfence();
        unsigned t = atomicAdd(&g_ticket, 1u);
        s_last = (t == NCTAS - 1);
    }
    __syncthreads();
    if (s_last) {
        __threadfence();
        __shared__ double fin[3][8];
        double loss = 0.0;
        for (int b = 0; b < BATCH; b++) {
            int j0 = b * 256 + tid;                 // batch b owns CTAs [b*256, b*256+256)
            double i0 = g_cta[j0][0];
            double a0 = g_cta[j0][1];
            double t0 = g_cta[j0][2];
#pragma unroll
            for (int o = 16; o > 0; o >>= 1) {
                i0 += __shfl_down_sync(0xffffffffu, i0, o);
                a0 += __shfl_down_sync(0xffffffffu, a0, o);
                t0 += __shfl_down_sync(0xffffffffu, t0, o);
            }
            if (lane == 0) { fin[0][wid] = i0; fin[1][wid] = a0; fin[2][wid] = t0; }
            __syncthreads();
            if (tid == 0) {
                double I = 0.0, A = 0.0, T = 0.0;
#pragma unroll
                for (int q = 0; q < 8; q++) { I += fin[0][q]; A += fin[1][q]; T += fin[2][q]; }
                loss += (T == 0.0) ? 0.0 : (1.0 - 2.0 * I / (A + T + 2.0e-6));
            }
            __syncthreads();
        }
        if (tid == 0) {
            out[0] = (float)(loss * 0.5);           // mean over BATCH=2
            g_bar1 = 0u; g_bar2 = 0u; g_ticket = 0u;
        }
    }
}

extern "C" void kernel_launch(void* const* d_in, const int* in_sizes, int n_in,
                              void* d_out, int out_size) {
    const float* outputs = (const float*)d_in[0];  // float32 [2,1,64,256,256]
    const int*   masks   = (const int*)d_in[1];    // int32   [2,1,64,256,256]
    float* out = (float*)d_out;

    cudaFuncSetAttribute(bbsd_one_kernel,
                         cudaFuncAttributeMaxDynamicSharedMemorySize, SMEM_BYTES);
    bbsd_one_kernel<<<NCTAS, THREADS, SMEM_BYTES>>>(outputs, masks, out);
}

// round 16
// speedup vs baseline: 1.9332x; 1.0460x over previous
#include <cuda_runtime.h>
#include <stdint.h>

// Geometry fixed by the problem: outputs/masks are [2,1,64,256,256]
#define HH 256
#define BATCH 2
#define SLICES 128
#define NCTA 1024                    // 8 CTAs (cluster) per slice
#define THREADS 256
#define CLR 8                        // cluster size / CTAs per slice
#define ROWS_PER_CTA 32
#define WORDS_PER_CTA 256            // 32 rows x 8 words

__device__ uint32_t g_pl[5][NCTA][WORDS_PER_CTA];  // rare slow-path planes
__device__ double   g_cta[NCTA][3];
__device__ unsigned g_ticket = 0;

__device__ __forceinline__ uint32_t my_rank() {
    uint32_t r;
    asm("mov.u32 %0, %%cluster_ctarank;" : "=r"(r));
    return r;
}
__device__ __forceinline__ uint32_t remote_ld(uint32_t saddr, uint32_t rank) {
    uint32_t ra, v;
    asm volatile("mapa.shared::cluster.u32 %0, %1, %2;" : "=r"(ra) : "r"(saddr), "r"(rank));
    asm volatile("ld.shared::cluster.u32 %0, [%1];" : "=r"(v) : "r"(ra) : "memory");
    return v;
}
__device__ __forceinline__ void cluster_sync() {
    asm volatile("barrier.cluster.arrive.aligned;" ::: "memory");
    asm volatile("barrier.cluster.wait.aligned;" ::: "memory");
}

__global__ __launch_bounds__(THREADS, 5) __cluster_dims__(CLR, 1, 1)
void bbsd_cluster_kernel(const float* __restrict__ outp, const int* __restrict__ mskp,
                         float* __restrict__ out) {
    __shared__ uint32_t mb[WORDS_PER_CTA];    // own mask bits
    __shared__ uint32_t b0[WORDS_PER_CTA];    // cascade double buffer
    __shared__ uint32_t b1[WORDS_PER_CTA];
    __shared__ int      bs_s[WORDS_PER_CTA];  // per-word LUT base; -100 = slow
    __shared__ uint32_t hm_s[WORDS_PER_CTA];  // per-word acc==ktop mask
    __shared__ uint32_t flag_s[8];            // [0] = my saturation flag
    __shared__ float lut[64];
    __shared__ double r0s[8], r1s[8], r2s[8];
    __shared__ int s_last;

    const int cta = blockIdx.x;
    const int slice = cta >> 3;
    const uint32_t rank = my_rank();
    const int tid = threadIdx.x;
    const int lane = tid & 31;
    const int wid = tid >> 5;

    const uint32_t mb_sa = (uint32_t)__cvta_generic_to_shared(mb);
    const uint32_t b0_sa = (uint32_t)__cvta_generic_to_shared(b0);
    const uint32_t b1_sa = (uint32_t)__cvta_generic_to_shared(b1);

    // weight LUT: acc 0..21; dist=(22-acc)/22; w=2/(1+exp(10*dist)); padded
    if (tid < 64) {
        int a = tid < 22 ? tid : 21;
        float dist = (22.0f - (float)a) / 22.0f;
        lut[tid] = 2.0f / (1.0f + expf(10.0f * dist));
    }

    // ---- pack own 32 rows of masks (8192 px) into smem bits ----
    const size_t pxbase = (size_t)slice * 65536 + (size_t)rank * 8192;
    const int4* mp4 = reinterpret_cast<const int4*>(mskp) + (pxbase >> 2);
#pragma unroll
    for (int h = 0; h < 2; h++) {
        int4 va[4];
#pragma unroll
        for (int j = 0; j < 4; j++)
            va[j] = mp4[(h * 4 + j) * 256 + tid];
#pragma unroll
        for (int j = 0; j < 4; j++) {
            int4 v = va[j];
            unsigned nib = (v.x ? 1u : 0u) | (v.y ? 2u : 0u)
                         | (v.z ? 4u : 0u) | (v.w ? 8u : 0u);
            unsigned w = nib << ((lane & 7) * 4);
            w |= __shfl_xor_sync(0xffffffffu, w, 1);
            w |= __shfl_xor_sync(0xffffffffu, w, 2);
            w |= __shfl_xor_sync(0xffffffffu, w, 4);
            int g = (h * 4 + j) * 256 + tid;
            if ((lane & 7) == 0) mb[g >> 3] = w;
        }
    }
    cluster_sync();                           // all 8 CTAs' mask bits visible

    // thread owns one word: local row = tid>>3 (0..31), col = tid&7
    const int row = tid >> 3;
    const int col = tid & 7;
    uint32_t P0, P1, P2, P3, P4;              // acc (incl. edge), bit-sliced

    // ---- edge = m & ~(up & dn & lf & rt), halo rows via DSMEM ----
    {
        uint32_t m = mb[tid];
        uint32_t up = (row > 0) ? mb[tid - 8]
                    : (rank > 0 ? remote_ld(mb_sa + (248 + col) * 4, rank - 1) : 0u);
        uint32_t dn = (row < 31) ? mb[tid + 8]
                    : (rank < 7 ? remote_ld(mb_sa + col * 4, rank + 1) : 0u);
        uint32_t pv = col ? mb[tid - 1] : 0u;
        uint32_t nx = (col < 7) ? mb[tid + 1] : 0u;
        uint32_t lf = (m << 1) | (pv >> 31);
        uint32_t rt = (m >> 1) | (nx << 31);
        uint32_t e = m & ~(up & dn & lf & rt);
        b0[tid] = e;
        P0 = e; P1 = 0u; P2 = 0u; P3 = 0u; P4 = 0u;
    }
    if (tid == 0) flag_s[0] = 0u;
    cluster_sync();                           // edge buffers visible cluster-wide

    // ---- cascade: per-round DSMEM halo + cluster saturation consensus ----
    int extra = 0;
    int sb = 0;
    for (int r = 1; r <= 20; r++) {
        const uint32_t* src = sb ? b1 : b0;
        uint32_t* dst = sb ? b0 : b1;
        const uint32_t src_sa = sb ? b1_sa : b0_sa;

        // vertical OR of rows row-1..row+1 for cols col-1, col, col+1
        uint32_t vv[3];
#pragma unroll
        for (int d = 0; d < 3; d++) {
            int c = col + d - 1;
            uint32_t v = 0u;
            if (c >= 0 && c < 8) {
                v = src[row * 8 + c];
                if (row > 0) v |= src[row * 8 - 8 + c];
                else if (rank > 0) v |= remote_ld(src_sa + (248 + c) * 4, rank - 1);
                if (row < 31) v |= src[row * 8 + 8 + c];
                else if (rank < 7) v |= remote_ld(src_sa + c * 4, rank + 1);
            }
            vv[d] = v;
        }
        uint32_t c0 = vv[1];
        uint32_t nw = c0 | (c0 << 1) | (vv[0] >> 31) | (c0 >> 1) | (vv[2] << 31);
        dst[tid] = nw;
        {   // ripple-carry +1 where covered
            uint32_t cy = nw, t;
            t = P0 & cy; P0 ^= cy; cy = t;
            t = P1 & cy; P1 ^= cy; cy = t;
            t = P2 & cy; P2 ^= cy; cy = t;
            t = P3 & cy; P3 ^= cy; cy = t;
            P4 ^= cy;
        }
        int sat = __syncthreads_and(nw == 0xffffffffu);   // also orders dst writes
        if (tid == 0) flag_s[0] = (unsigned)sat;
        cluster_sync();                        // publish dst + flag
        // consensus: threads 0..7 read each rank's flag; AND across CTA
        bool mydone = true;
        if (tid < 8) mydone = (remote_ld((uint32_t)__cvta_generic_to_shared(flag_s), tid) != 0u);
        sb ^= 1;
        if (__syncthreads_and(mydone)) { extra = 20 - r; break; }
    }

    // ---- per-word metadata: acc two-valued {kt-1, kt} (typical) ----
    {
        uint32_t p0 = P0, p1 = P1, p2 = P2, p3 = P3, p4 = P4;
        unsigned kt = ((p0 >> 31) & 1u) | (((p1 >> 31) & 1u) << 1)
                    | (((p2 >> 31) & 1u) << 2) | (((p3 >> 31) & 1u) << 3)
                    | (((p4 >> 31) & 1u) << 4);
        uint32_t mhi = ((kt & 1u)  ? p0 : ~p0) & ((kt & 2u)  ? p1 : ~p1)
                     & ((kt & 4u)  ? p2 : ~p2) & ((kt & 8u)  ? p3 : ~p3)
                     & ((kt & 16u) ? p4 : ~p4);
        uint32_t mlo = 0u;
        if (kt) {
            unsigned kl = kt - 1u;
            mlo = ((kl & 1u)  ? p0 : ~p0) & ((kl & 2u)  ? p1 : ~p1)
                & ((kl & 4u)  ? p2 : ~p2) & ((kl & 8u)  ? p3 : ~p3)
                & ((kl & 16u) ? p4 : ~p4);
        }
        bool valid = (mhi | mlo) == 0xffffffffu;
        bs_s[tid] = valid ? ((int)kt - 1 + extra) : -100;
        hm_s[tid] = mhi;
        if (!valid) {
            g_pl[0][cta][tid] = p0; g_pl[1][cta][tid] = p1; g_pl[2][cta][tid] = p2;
            g_pl[3][cta][tid] = p3; g_pl[4][cta][tid] = p4;
        }
    }
    __syncthreads();

    // ---- decode own 32 rows of outputs (8192 px), meta from smem ----
    const float4* op4 = reinterpret_cast<const float4*>(outp) + (pxbase >> 2);
    float s_ia = 0.f, s_in = 0.f, s_ta = 0.f;
#pragma unroll
    for (int h = 0; h < 2; h++) {
        float4 va[4];
#pragma unroll
        for (int j = 0; j < 4; j++)
            va[j] = op4[(h * 4 + j) * 256 + tid];
#pragma unroll
        for (int j = 0; j < 4; j++) {
            int g = (h * 4 + j) * 256 + tid;
            int lw = g >> 3;
            int i0 = (g & 7) * 4;
            int bs = bs_s[lw];
            uint32_t qm = mb[lw] >> i0;
            float vv4[4] = {va[j].x, va[j].y, va[j].z, va[j].w};
            if (bs != -100) {
                uint32_t qh = hm_s[lw] >> i0;
#pragma unroll
                for (int e = 0; e < 4; e++) {
                    float w = lut[bs + (int)((qh >> e) & 1u)];
                    float f = vv4[e] * w;
                    s_ia += f;
                    if ((qm >> e) & 1u) { s_in += f; s_ta += w; }
                }
            } else {
                uint32_t q0 = g_pl[0][cta][lw] >> i0;
                uint32_t q1 = g_pl[1][cta][lw] >> i0;
                uint32_t q2 = g_pl[2][cta][lw] >> i0;
                uint32_t q3 = g_pl[3][cta][lw] >> i0;
                uint32_t q4 = g_pl[4][cta][lw] >> i0;
#pragma unroll
                for (int e = 0; e < 4; e++) {
                    unsigned a = ((q0 >> e) & 1u)
                               | (((q1 >> e) & 1u) << 1)
                               | (((q2 >> e) & 1u) << 2)
                               | (((q3 >> e) & 1u) << 3)
                               | (((q4 >> e) & 1u) << 4);
                    float w = lut[a + extra];
                    float f = vv4[e] * w;
                    s_ia += f;
                    if ((qm >> e) & 1u) { s_in += f; s_ta += w; }
                }
            }
        }
    }

    // ---- reduce to per-CTA partials ----
    double d0 = (double)s_in, d1 = (double)s_ia, d2 = (double)s_ta;
#pragma unroll
    for (int o = 16; o > 0; o >>= 1) {
        d0 += __shfl_down_sync(0xffffffffu, d0, o);
        d1 += __shfl_down_sync(0xffffffffu, d1, o);
        d2 += __shfl_down_sync(0xffffffffu, d2, o);
    }
    if (lane == 0) { r0s[wid] = d0; r1s[wid] = d1; r2s[wid] = d2; }
    __syncthreads();
    if (wid == 0) {
        double a0 = (lane < 8) ? r0s[lane] : 0.0;
        double a1 = (lane < 8) ? r1s[lane] : 0.0;
        double a2 = (lane < 8) ? r2s[lane] : 0.0;
#pragma unroll
        for (int o = 4; o > 0; o >>= 1) {
            a0 += __shfl_down_sync(0xffffffffu, a0, o);
            a1 += __shfl_down_sync(0xffffffffu, a1, o);
            a2 += __shfl_down_sync(0xffffffffu, a2, o);
        }
        if (lane == 0) {
            g_cta[cta][0] = a0;
            g_cta[cta][1] = a1;
            g_cta[cta][2] = a2;
        }
    }

    // ---- fused finalize: last-arriving CTA computes loss; reset state ----
    if (tid == 0) {
        __threadfence();
        unsigned t = atomicAdd(&g_ticket, 1u);
        s_last = (t == NCTA - 1);
    }
    __syncthreads();
    if (s_last) {
        __threadfence();
        __shared__ double fin[3][8];
        double loss = 0.0;
        for (int b = 0; b < BATCH; b++) {
            int j0 = b * 512 + tid;               // batch b owns CTAs [b*512, b*512+512)
            double i0 = g_cta[j0][0] + g_cta[j0 + 256][0];
            double a0 = g_cta[j0][1] + g_cta[j0 + 256][1];
            double t0 = g_cta[j0][2] + g_cta[j0 + 256][2];
#pragma unroll
            for (int o = 16; o > 0; o >>= 1) {
                i0 += __shfl_down_sync(0xffffffffu, i0, o);
                a0 += __shfl_down_sync(0xffffffffu, a0, o);
                t0 += __shfl_down_sync(0xffffffffu, t0, o);
            }
            if (lane == 0) { fin[0][wid] = i0; fin[1][wid] = a0; fin[2][wid] = t0; }
            __syncthreads();
            if (tid == 0) {
                double I = 0.0, A = 0.0, T = 0.0;
#pragma unroll
                for (int q = 0; q < 8; q++) { I += fin[0][q]; A += fin[1][q]; T += fin[2][q]; }
                loss += (T == 0.0) ? 0.0 : (1.0 - 2.0 * I / (A + T + 2.0e-6));
            }
            __syncthreads();
        }
        if (tid == 0) {
            out[0] = (float)(loss * 0.5);         // mean over BATCH=2
            g_ticket = 0u;                        // reset for next graph replay
        }
    }
}

extern "C" void kernel_launch(void* const* d_in, const int* in_sizes, int n_in,
                              void* d_out, int out_size) {
    const float* outputs = (const float*)d_in[0];  // float32 [2,1,64,256,256]
    const int*   masks   = (const int*)d_in[1];    // int32   [2,1,64,256,256]
    float* out = (float*)d_out;

    bbsd_cluster_kernel<<<NCTA, THREADS>>>(outputs, masks, out);
}

// round 17
// speedup vs baseline: 2.7440x; 1.4194x over previous
#include <cuda_runtime.h>
#include <stdint.h>

// Geometry fixed by the problem: outputs/masks are [2,1,64,256,256]
#define HH 256
#define WW 256
#define BATCH 2
#define SLICES 128                 // 2*64 independent 2D slices
#define WPR 8                      // 32-bit words per 256-px row
#define NWORDS (HH * WPR)          // 2048 words per slice bitmask
#define NPIX (HH * WW)             // 65536 px per slice
#define NTHREADS 1024

// Per-slice partial sums + rare slow-path plane spill
__device__ double   g_part[SLICES][3];
__device__ uint32_t g_pl[5][SLICES][NWORDS];   // written only for rare words
__device__ unsigned g_ticket = 0;

// asm-pinned vector loads: ptxas cannot reorder/collapse these -> true MLP
__device__ __forceinline__ int4 ldg_nc_i4(const int4* p) {
    int4 v;
    asm volatile("ld.global.nc.v4.s32 {%0,%1,%2,%3}, [%4];"
                 : "=r"(v.x), "=r"(v.y), "=r"(v.z), "=r"(v.w) : "l"(p));
    return v;
}
__device__ __forceinline__ float4 ldg_nc_f4(const float4* p) {
    float4 v;
    asm volatile("ld.global.nc.v4.f32 {%0,%1,%2,%3}, [%4];"
                 : "=f"(v.x), "=f"(v.y), "=f"(v.z), "=f"(v.w) : "l"(p));
    return v;
}

__global__ __launch_bounds__(NTHREADS, 1)
void bbsd_slice_kernel(const float* __restrict__ outp, const int* __restrict__ mskp,
                       float* __restrict__ out) {
    __shared__ uint32_t mb[NWORDS];          // mask bits (8 KB)
    __shared__ uint32_t eb[NWORDS];          // edge bits (8 KB)
    __shared__ uint32_t scratch[5 * 1024];   // cascade bufs (16K) / plane spill (20K), aliased
    __shared__ int      wb_s[1024];          // per-word base index (one half)  (4 KB)
    __shared__ uint32_t hm_s[1024];          // per-word K==ktop bitmask        (4 KB)
    __shared__ float lut[64];
    __shared__ double red0[32], red1[32], red2[32];
    __shared__ int s_last;

    const int slice = blockIdx.x;
    const size_t base = (size_t)slice * NPIX;
    const int tid = threadIdx.x;
    const int lane = tid & 31;
    const int wid = tid >> 5;

    // weight LUT: acc in 0..21; dist=(22-acc)/22; w=2/(1+exp(10*dist)); padded
    if (tid < 64) {
        int a = tid < 22 ? tid : 21;
        float dist = (22.0f - (float)a) / 22.0f;
        lut[tid] = 2.0f / (1.0f + expf(10.0f * dist));
    }

    // ---- pack mask: 2 batches of 8 asm-pinned int4 loads (true MLP=8) ----
    const int4* mp4 = reinterpret_cast<const int4*>(mskp + base);
#pragma unroll
    for (int h = 0; h < 2; h++) {
        int4 va[8];
#pragma unroll
        for (int j = 0; j < 8; j++)
            va[j] = ldg_nc_i4(mp4 + (h * 8 + j) * NTHREADS + tid);
#pragma unroll
        for (int j = 0; j < 8; j++) {
            int4 v = va[j];
            unsigned nib = (v.x != 0 ? 1u : 0u) | (v.y != 0 ? 2u : 0u)
                         | (v.z != 0 ? 4u : 0u) | (v.w != 0 ? 8u : 0u);
            unsigned w = nib << ((lane & 7) * 4);
            w |= __shfl_xor_sync(0xffffffffu, w, 1);
            w |= __shfl_xor_sync(0xffffffffu, w, 2);
            w |= __shfl_xor_sync(0xffffffffu, w, 4);
            int g = (h * 8 + j) * NTHREADS + tid;
            if ((lane & 7) == 0) mb[g >> 3] = w;
        }
    }
    __syncthreads();

    // thread owns a quarter-row: 2 consecutive words (word index = 2*tid)
    const int row = tid >> 2;
    const int cw0 = (tid & 3) * 2;
    const int wb = row * WPR + cw0;

    // 5-plane bit-sliced coverage counters K (rounds only; edge kept separate)
    uint32_t P0[2], P1[2], P2[2], P3[2], P4[2];

    // ---- edge: m & ~(up & down & left & right), zero padded ----
#pragma unroll
    for (int j = 0; j < 2; j++) {
        int cw = cw0 + j, gw = wb + j;
        uint32_t m  = mb[gw];
        uint32_t up = row            ? mb[gw - WPR] : 0u;
        uint32_t dn = (row < HH - 1) ? mb[gw + WPR] : 0u;
        uint32_t pv = cw             ? mb[gw - 1]   : 0u;
        uint32_t nx = (cw < WPR - 1) ? mb[gw + 1]   : 0u;
        uint32_t lf = (m << 1) | (pv >> 31);
        uint32_t rt = (m >> 1) | (nx << 31);
        uint32_t e = m & ~(up & dn & lf & rt);
        scratch[gw] = e;                 // dilation src buffer 0
        eb[gw] = e;
        P0[j] = 0u; P1[j] = 0u; P2[j] = 0u; P3[j] = 0u; P4[j] = 0u;
    }
    __syncthreads();

    // ---- cascaded 3x3 OR-dilations with saturation early-exit ----
    int extra = 0;
    int sb = 0;
    for (int r = 1; r <= 20; r++) {
        const uint32_t* src = scratch + sb * 2048;
        uint32_t* dst = scratch + (sb ^ 1) * 2048;
        uint32_t va[4];
#pragma unroll
        for (int k = 0; k < 4; k++) {
            int cw = cw0 + k - 1;
            uint32_t v = 0u;
            if (cw >= 0 && cw < WPR) {
                int gw = row * WPR + cw;
                v = src[gw];
                if (row)          v |= src[gw - WPR];
                if (row < HH - 1) v |= src[gw + WPR];
            }
            va[k] = v;
        }
        uint32_t allw = 0xffffffffu;
#pragma unroll
        for (int j = 0; j < 2; j++) {
            uint32_t c = va[j + 1];
            uint32_t nw = c | (c << 1) | (va[j] >> 31) | (c >> 1) | (va[j + 2] << 31);
            dst[wb + j] = nw;
            allw &= nw;
            uint32_t cy = nw, t;         // ripple-carry +1 where covered
            t = P0[j] & cy; P0[j] ^= cy; cy = t;
            t = P1[j] & cy; P1[j] ^= cy; cy = t;
            t = P2[j] & cy; P2[j] ^= cy; cy = t;
            t = P3[j] & cy; P3[j] ^= cy; cy = t;
            P4[j] ^= cy;
        }
        sb ^= 1;
        if (__syncthreads_and(allw == 0xffffffffu)) { extra = 20 - r; break; }
    }

    // ---- per-half: spill planes + per-word decode metadata, then decode ----
    float s_ia = 0.f, s_in = 0.f, s_ta = 0.f;
    for (int half = 0; half < 2; half++) {
        __syncthreads();   // planes/meta of previous half fully consumed
        if ((row >> 7) == half) {
            int lw = ((row & 127) * WPR + cw0);      // local word index in half
#pragma unroll
            for (int j = 0; j < 2; j++) {
                uint32_t p0 = P0[j], p1 = P1[j], p2 = P2[j], p3 = P3[j], p4 = P4[j];
                scratch[0 * 1024 + lw + j] = p0;     // plane spill (aliases dead bufs)
                scratch[1 * 1024 + lw + j] = p1;
                scratch[2 * 1024 + lw + j] = p2;
                scratch[3 * 1024 + lw + j] = p3;
                scratch[4 * 1024 + lw + j] = p4;
                // k_top = K of bit 31
                unsigned kt = ((p0 >> 31) & 1u) | (((p1 >> 31) & 1u) << 1)
                            | (((p2 >> 31) & 1u) << 2) | (((p3 >> 31) & 1u) << 3)
                            | (((p4 >> 31) & 1u) << 4);
                uint32_t mhi = ((kt & 1u)  ? p0 : ~p0) & ((kt & 2u)  ? p1 : ~p1)
                             & ((kt & 4u)  ? p2 : ~p2) & ((kt & 8u)  ? p3 : ~p3)
                             & ((kt & 16u) ? p4 : ~p4);
                uint32_t mlo = 0u;
                if (kt) {
                    unsigned kl = kt - 1u;
                    mlo = ((kl & 1u)  ? p0 : ~p0) & ((kl & 2u)  ? p1 : ~p1)
                        & ((kl & 4u)  ? p2 : ~p2) & ((kl & 8u)  ? p3 : ~p3)
                        & ((kl & 16u) ? p4 : ~p4);
                }
                bool valid = (mhi | mlo) == 0xffffffffu;
                wb_s[lw + j] = valid ? ((int)kt - 1 + extra) : -100;
                hm_s[lw + j] = mhi;
            }
        }
        __syncthreads();

        const float4* op4 = reinterpret_cast<const float4*>(outp + base + (size_t)half * (NPIX / 2));
        // one batch of 8 asm-pinned float4 loads covers this half (8192 groups)
        float4 va[8];
#pragma unroll
        for (int k = 0; k < 8; k++)
            va[k] = ldg_nc_f4(op4 + k * NTHREADS + tid);
#pragma unroll
        for (int k = 0; k < 8; k++) {
            int g = k * NTHREADS + tid;
            int lw = g >> 3;
            int i0 = (g & 7) * 4;
            int wbase = wb_s[lw];
            uint32_t qm = mb[half * 1024 + lw] >> i0;
            uint32_t qe = eb[half * 1024 + lw] >> i0;
            float vv[4] = {va[k].x, va[k].y, va[k].z, va[k].w};
            if (wbase != -100) {
                uint32_t qh = hm_s[lw] >> i0;
#pragma unroll
                for (int e = 0; e < 4; e++) {
                    int idx = wbase + (int)((qh >> e) & 1u) + (int)((qe >> e) & 1u);
                    float w = lut[idx];
                    float f = vv[e] * w;
                    s_ia += f;
                    if ((qm >> e) & 1u) { s_in += f; s_ta += w; }
                }
            } else {
                uint32_t q0 = scratch[0 * 1024 + lw] >> i0;
                uint32_t q1 = scratch[1 * 1024 + lw] >> i0;
                uint32_t q2 = scratch[2 * 1024 + lw] >> i0;
                uint32_t q3 = scratch[3 * 1024 + lw] >> i0;
                uint32_t q4 = scratch[4 * 1024 + lw] >> i0;
#pragma unroll
                for (int e = 0; e < 4; e++) {
                    unsigned a = ((q0 >> e) & 1u)
                               | (((q1 >> e) & 1u) << 1)
                               | (((q2 >> e) & 1u) << 2)
                               | (((q3 >> e) & 1u) << 3)
                               | (((q4 >> e) & 1u) << 4);
                    a += ((qe >> e) & 1u) + extra;
                    float w = lut[a];
                    float f = vv[e] * w;
                    s_ia += f;
                    if ((qm >> e) & 1u) { s_in += f; s_ta += w; }
                }
            }
        }
    }

    // ---- reduce to per-slice partials ----
    double d0 = (double)s_in, d1 = (double)s_ia, d2 = (double)s_ta;
#pragma unroll
    for (int o = 16; o > 0; o >>= 1) {
        d0 += __shfl_down_sync(0xffffffffu, d0, o);
        d1 += __shfl_down_sync(0xffffffffu, d1, o);
        d2 += __shfl_down_sync(0xffffffffu, d2, o);
    }
    if (lane == 0) { red0[wid] = d0; red1[wid] = d1; red2[wid] = d2; }
    __syncthreads();
    if (wid == 0) {
        double a0 = red0[lane];
        double a1 = red1[lane];
        double a2 = red2[lane];
#pragma unroll
        for (int o = 16; o > 0; o >>= 1) {
            a0 += __shfl_down_sync(0xffffffffu, a0, o);
            a1 += __shfl_down_sync(0xffffffffu, a1, o);
            a2 += __shfl_down_sync(0xffffffffu, a2, o);
        }
        if (lane == 0) {
            g_part[slice][0] = a0;
            g_part[slice][1] = a1;
            g_part[slice][2] = a2;
        }
    }

    // ---- fused finalize: last-arriving CTA computes the scalar loss ----
    if (tid == 0) {
        __threadfence();
        unsigned t = atomicAdd(&g_ticket, 1u);
        s_last = (t == SLICES - 1);
    }
    __syncthreads();
    if (s_last && wid == 0) {
        __threadfence();
        double loss = 0.0;
#pragma unroll
        for (int b = 0; b < BATCH; b++) {
            double i0 = g_part[b * 64 + lane][0] + g_part[b * 64 + 32 + lane][0];
            double a0 = g_part[b * 64 + lane][1] + g_part[b * 64 + 32 + lane][1];
            double t0 = g_part[b * 64 + lane][2] + g_part[b * 64 + 32 + lane][2];
#pragma unroll
            for (int o = 16; o > 0; o >>= 1) {
                i0 += __shfl_down_sync(0xffffffffu, i0, o);
                a0 += __shfl_down_sync(0xffffffffu, a0, o);
                t0 += __shfl_down_sync(0xffffffffu, t0, o);
            }
            if (lane == 0)
                loss += (t0 == 0.0) ? 0.0 : (1.0 - 2.0 * i0 / (a0 + t0 + 2.0e-6));
        }
        if (lane == 0) {
            out[0] = (float)(loss * 0.5);
            g_ticket = 0;
        }
    }
}

extern "C" void kernel_launch(void* const* d_in, const int* in_sizes, int n_in,
                              void* d_out, int out_size) {
    const float* outputs = (const float*)d_in[0];  // float32 [2,1,64,256,256]
    const int*   masks   = (const int*)d_in[1];    // int32   [2,1,64,256,256]
    float* out = (float*)d_out;

    bbsd_slice_kernel<<<SLICES, NTHREADS>>>(outputs, masks, out);
}